// round 6
// baseline (speedup 1.0000x reference)
#include <cuda_runtime.h>
#include <cuda_bf16.h>
#include <stdint.h>
#include <math.h>

// ---------------- problem constants ----------------
#define HDIM   512
#define HEADS  16
#define HD     32
#define WS     8
#define L      64
#define NW     1024
#define NTOK   65536
#define IMG    256
#define NPIX   65536

typedef __nv_bfloat16 bf16;
typedef __nv_bfloat162 bf162;

#define WSCALE     32.0f
#define INV_WSCALE 0.03125f

// ---------------- scratch ----------------
__device__ float g_win[(size_t)NTOK * HDIM];
__device__ float g_o1[(size_t)NTOK * HDIM];
__device__ __align__(16) uint8_t g_xn8[(size_t)NTOK * HDIM];       // LN out fp8
__device__ __align__(16) bf16    g_qkvb[(size_t)NTOK * 3 * HDIM];  // qkv bf16
__device__ __align__(16) uint8_t g_att8[(size_t)NTOK * HDIM];      // attn out fp8
__device__ __align__(16) uint8_t g_h8[(size_t)NTOK * 4 * HDIM];    // mlp hidden fp8
// transposed fp8 weights [N, K], pre-scaled by 32
__device__ __align__(16) uint8_t g_wq8[(size_t)3 * HDIM * HDIM];
__device__ __align__(16) uint8_t g_wp8[(size_t)HDIM * HDIM];
__device__ __align__(16) uint8_t g_w18[(size_t)4 * HDIM * HDIM];
__device__ __align__(16) uint8_t g_w28[(size_t)HDIM * 4 * HDIM];

#define CP_ASYNC16(dst, src) \
    asm volatile("cp.async.cg.shared.global [%0], [%1], 16;\n" :: "r"(dst), "l"(src))

__device__ __forceinline__ unsigned sptr(const void* p) {
    return (unsigned)__cvta_generic_to_shared(p);
}
__device__ __forceinline__ unsigned packbf(float x, float y) {
    bf162 t = __floats2bfloat162_rn(x, y);
    return *(unsigned*)&t;
}
// pack two floats to e4m3 pair: low byte = x, high byte = y
__device__ __forceinline__ unsigned short pack8(float x, float y) {
    unsigned short r;
    asm("cvt.rn.satfinite.e4m3x2.f32 %0, %1, %2;" : "=h"(r) : "f"(y), "f"(x));
    return r;
}

// ---------------- weight transpose fp32[K,N] -> fp8[N,K] * 32 --------------
__global__ void wtrans_kernel(const float* __restrict__ in, uint8_t* __restrict__ out,
                              int K, int N)
{
    __shared__ float tile[32][33];
    int k0 = blockIdx.x * 32;
    int n0 = blockIdx.y * 32;
    int tx = threadIdx.x, ty = threadIdx.y;
#pragma unroll
    for (int cc = 0; cc < 4; cc++)
        tile[ty + cc * 8][tx] = in[(size_t)(k0 + ty + cc * 8) * N + n0 + tx];
    __syncthreads();
#pragma unroll
    for (int cc = 0; cc < 4; cc++) {
        float v = tile[tx][ty + cc * 8] * WSCALE;
        out[(size_t)(n0 + ty + cc * 8) * K + k0 + tx] = (uint8_t)pack8(v, 0.f);
    }
}

// ---------------- roll + window partition ----------------
__global__ void partition_kernel(const float* __restrict__ x, float* __restrict__ win)
{
    __shared__ float tile[32][33];
    int t0 = blockIdx.x * 32;
    int c0 = blockIdx.y * 32;
    int tx = threadIdx.x;
    int ty = threadIdx.y;

    int t  = t0 + tx;
    int w  = t >> 6;
    int l  = t & 63;
    int hb = w >> 5, wb = w & 31;
    int ii = l >> 3, jj = l & 7;
    int sh = (hb * 8 + ii + 4) & 255;
    int sw = (wb * 8 + jj + 4) & 255;
    int pix = sh * IMG + sw;

#pragma unroll
    for (int cc = 0; cc < 4; cc++) {
        int c = c0 + ty + cc * 8;
        tile[ty + cc * 8][tx] = x[(size_t)c * NPIX + pix];
    }
    __syncthreads();
#pragma unroll
    for (int cc = 0; cc < 4; cc++) {
        int tt = ty + cc * 8;
        win[(size_t)(t0 + tt) * HDIM + c0 + tx] = tile[tx][tt];
    }
}

// ---------------- window reverse ----------------
__global__ void reverse_kernel(const float* __restrict__ o2, float* __restrict__ out)
{
    __shared__ float tile[32][33];
    int t0 = blockIdx.x * 32;
    int c0 = blockIdx.y * 32;
    int tx = threadIdx.x;
    int ty = threadIdx.y;

#pragma unroll
    for (int cc = 0; cc < 4; cc++) {
        int tt = ty + cc * 8;
        tile[tt][tx] = o2[(size_t)(t0 + tt) * HDIM + c0 + tx];
    }
    __syncthreads();

    int t  = t0 + tx;
    int w  = t >> 6;
    int l  = t & 63;
    int hb = w >> 5, wb = w & 31;
    int ii = l >> 3, jj = l & 7;
    int dh = (hb * 8 + ii + 4) & 255;
    int dw = (wb * 8 + jj + 4) & 255;
    int pix = dh * IMG + dw;

#pragma unroll
    for (int cc = 0; cc < 4; cc++) {
        int c = c0 + ty + cc * 8;
        out[(size_t)c * NPIX + pix] = tile[tx][ty + cc * 8];
    }
}

// ---------------- LayerNorm -> fp8 ----------------
__global__ void ln_kernel(const float* __restrict__ in, uint8_t* __restrict__ out,
                          const float* __restrict__ w, const float* __restrict__ b)
{
    int warp = (blockIdx.x * blockDim.x + threadIdx.x) >> 5;
    int lane = threadIdx.x & 31;
    if (warp >= NTOK) return;
    const float* row = in + (size_t)warp * HDIM;

    float4 v[4];
    float sum = 0.f, sq = 0.f;
#pragma unroll
    for (int i = 0; i < 4; i++) {
        v[i] = *(const float4*)(row + (size_t)(i * 32 + lane) * 4);
        sum += v[i].x + v[i].y + v[i].z + v[i].w;
        sq  += v[i].x * v[i].x + v[i].y * v[i].y + v[i].z * v[i].z + v[i].w * v[i].w;
    }
#pragma unroll
    for (int o = 16; o; o >>= 1) {
        sum += __shfl_xor_sync(0xffffffffu, sum, o);
        sq  += __shfl_xor_sync(0xffffffffu, sq, o);
    }
    float mu  = sum * (1.f / HDIM);
    float var = sq * (1.f / HDIM) - mu * mu;
    float inv = rsqrtf(var + 1e-5f);

    uint8_t* orow = out + (size_t)warp * HDIM;
#pragma unroll
    for (int i = 0; i < 4; i++) {
        int c = (i * 32 + lane) * 4;
        float4 wv = *(const float4*)(w + c);
        float4 bv = *(const float4*)(b + c);
        float rx = (v[i].x - mu) * inv * wv.x + bv.x;
        float ry = (v[i].y - mu) * inv * wv.y + bv.y;
        float rz = (v[i].z - mu) * inv * wv.z + bv.z;
        float rw = (v[i].w - mu) * inv * wv.w + bv.w;
        unsigned packed = (unsigned)pack8(rx, ry) | ((unsigned)pack8(rz, rw) << 16);
        *(unsigned*)(orow + c) = packed;
    }
}

// ---------------- fp8 tensor-core GEMM ------------------------------------
// C[M,N] = epi(A[M,K] @ Bt[N,K]^T * (1/32) + bias)
// A, Bt are e4m3; Bt pre-scaled by 32. Tiles 128x128x64(bytes).
// EPI 0: +bias (bf16 out)  1: +bias -> GELU (fp8 out)  2: res + gamma*(+bias) (f32 out)
#define QBM 128
#define QBN 128
#define QBK 64
#define QPITCH 80                   // 64 + 16 pad
#define QSTAGE (QBM * QPITCH)       // 10240 per tile per stage
#define QSMEM  (6 * QSTAGE)         // 3 stages x (A + B)

template <int EPI, typename CT>
__global__ void __launch_bounds__(256) qgemm_kernel(
    const uint8_t* __restrict__ A, const uint8_t* __restrict__ Bt,
    const float* __restrict__ bias, CT* __restrict__ C,
    int M, int N, int K,
    const float* __restrict__ res, const float* __restrict__ gamma)
{
    extern __shared__ uint8_t dsm[];
    uint8_t* As = dsm;                    // [3][128][80]
    uint8_t* Bs = dsm + 3 * QSTAGE;       // [3][128][80]

    int tid  = threadIdx.x;
    int lane = tid & 31;
    int warp = tid >> 5;
    int wm = warp >> 2;                   // 0..1
    int wn = warp & 3;                    // 0..3
    int row0 = blockIdx.y * QBM;
    int col0 = blockIdx.x * QBN;

    const uint8_t* Ab = A  + (size_t)row0 * K;
    const uint8_t* Bb = Bt + (size_t)col0 * K;

    // per-thread load coords: 512 chunks of 16B per tile, 2 per thread
    int r0c = (tid * 2) >> 2,     c0c = ((tid * 2) & 3) * 16;
    int r1c = (tid * 2 + 1) >> 2, c1c = ((tid * 2 + 1) & 3) * 16;

#define QLOAD(buf, k0)                                                          \
    do {                                                                        \
        CP_ASYNC16(sptr(As + (buf) * QSTAGE + r0c * QPITCH + c0c),              \
                   Ab + (size_t)r0c * K + (k0) + c0c);                          \
        CP_ASYNC16(sptr(As + (buf) * QSTAGE + r1c * QPITCH + c1c),              \
                   Ab + (size_t)r1c * K + (k0) + c1c);                          \
        CP_ASYNC16(sptr(Bs + (buf) * QSTAGE + r0c * QPITCH + c0c),              \
                   Bb + (size_t)r0c * K + (k0) + c0c);                          \
        CP_ASYNC16(sptr(Bs + (buf) * QSTAGE + r1c * QPITCH + c1c),              \
                   Bb + (size_t)r1c * K + (k0) + c1c);                          \
        asm volatile("cp.async.commit_group;" ::: "memory");                    \
    } while (0)

    float acc[4][4][4];
#pragma unroll
    for (int mi = 0; mi < 4; mi++)
#pragma unroll
        for (int ni = 0; ni < 4; ni++)
#pragma unroll
            for (int r = 0; r < 4; r++) acc[mi][ni][r] = 0.f;

    int nk = K / QBK;
    QLOAD(0, 0);
    QLOAD(1, QBK);

    int buf = 0, nbuf = 2;
    for (int kt = 0; kt < nk; kt++) {
        asm volatile("cp.async.wait_group 1;" ::: "memory");
        __syncthreads();
        if (kt + 2 < nk) {
            int k0 = (kt + 2) * QBK;
            QLOAD(nbuf, k0);
        } else {
            asm volatile("cp.async.commit_group;" ::: "memory");
        }

#pragma unroll
        for (int kk = 0; kk < 2; kk++) {
            unsigned a[4][4], b[4][2];
#pragma unroll
            for (int mi = 0; mi < 4; mi++) {
                unsigned addr = sptr(As + buf * QSTAGE
                    + (wm * 64 + mi * 16 + (lane & 15)) * QPITCH
                    + kk * 32 + (lane >> 4) * 16);
                asm volatile("ldmatrix.sync.aligned.m8n8.x4.shared.b16 {%0,%1,%2,%3},[%4];"
                    : "=r"(a[mi][0]), "=r"(a[mi][1]), "=r"(a[mi][2]), "=r"(a[mi][3])
                    : "r"(addr));
            }
#pragma unroll
            for (int ni = 0; ni < 4; ni++) {
                unsigned addr = sptr(Bs + buf * QSTAGE
                    + (wn * 32 + ni * 8 + (lane & 7)) * QPITCH
                    + kk * 32 + ((lane >> 3) & 1) * 16);
                asm volatile("ldmatrix.sync.aligned.m8n8.x2.shared.b16 {%0,%1},[%2];"
                    : "=r"(b[ni][0]), "=r"(b[ni][1]) : "r"(addr));
            }
#pragma unroll
            for (int mi = 0; mi < 4; mi++)
#pragma unroll
                for (int ni = 0; ni < 4; ni++)
                    asm volatile("mma.sync.aligned.m16n8k32.row.col.f32.e4m3.e4m3.f32 "
                        "{%0,%1,%2,%3},{%4,%5,%6,%7},{%8,%9},{%0,%1,%2,%3};"
                        : "+f"(acc[mi][ni][0]), "+f"(acc[mi][ni][1]),
                          "+f"(acc[mi][ni][2]), "+f"(acc[mi][ni][3])
                        : "r"(a[mi][0]), "r"(a[mi][1]), "r"(a[mi][2]), "r"(a[mi][3]),
                          "r"(b[ni][0]), "r"(b[ni][1]));
        }
        buf = (buf + 1) % 3;
        nbuf = (nbuf + 1) % 3;
    }

    int lr = lane >> 2;
    int lc = (lane & 3) * 2;
#pragma unroll
    for (int mi = 0; mi < 4; mi++) {
#pragma unroll
        for (int half = 0; half < 2; half++) {
            int grow = row0 + wm * 64 + mi * 16 + lr + half * 8;
#pragma unroll
            for (int ni = 0; ni < 4; ni++) {
                int gcol = col0 + wn * 32 + ni * 8 + lc;
                float v0 = acc[mi][ni][half * 2 + 0] * INV_WSCALE + bias[gcol];
                float v1 = acc[mi][ni][half * 2 + 1] * INV_WSCALE + bias[gcol + 1];
                if (EPI == 1) {
                    v0 = 0.5f * v0 * (1.f + erff(v0 * 0.70710678118f));
                    v1 = 0.5f * v1 * (1.f + erff(v1 * 0.70710678118f));
                }
                if (EPI == 2) {
                    const float* rp = res + (size_t)grow * N + gcol;
                    v0 = rp[0] + gamma[gcol] * v0;
                    v1 = rp[1] + gamma[gcol + 1] * v1;
                }
                if (sizeof(CT) == 4) {
                    float* cp = (float*)C + (size_t)grow * N + gcol;
                    cp[0] = v0; cp[1] = v1;
                } else if (sizeof(CT) == 2) {
                    bf16* cp = (bf16*)C + (size_t)grow * N + gcol;
                    *(bf162*)cp = __floats2bfloat162_rn(v0, v1);
                } else {
                    uint8_t* cp = (uint8_t*)C + (size_t)grow * N + gcol;
                    *(unsigned short*)cp = pack8(v0, v1);
                }
            }
        }
    }
}

// ---------------- tensor-core attention (bf16 in, fp8 out) -----------------
__global__ void __launch_bounds__(128) attn_mma_kernel(
    const bf16* __restrict__ qkv, const float* __restrict__ rel_table,
    uint8_t* __restrict__ out)
{
    __shared__ bf16 qs[64][72], ks[64][72], vs[64][72];
    __shared__ float tbl[2][225];
    __shared__ int rg[64];

    int w    = blockIdx.x;
    int hb   = blockIdx.y;
    int tid  = threadIdx.x;
    int lane = tid & 31;
    int warp = tid >> 5;
    int hh   = warp >> 1;
    int wr   = warp & 1;

    for (int i = tid; i < 2 * 225; i += 128) {
        int h2 = i / 225, idx = i - h2 * 225;
        tbl[h2][idx] = rel_table[idx * HEADS + hb * 2 + h2];
    }
    if (tid < 64) {
        int hbw = w >> 5, wbw = w & 31;
        int ii = hbw * 8 + (tid >> 3);
        int jj = wbw * 8 + (tid & 7);
        int rh = (ii < 248) ? 0 : (ii < 252 ? 1 : 2);
        int rw = (jj < 248) ? 0 : (jj < 252 ? 1 : 2);
        rg[tid] = rh * 3 + rw;
    }

    const bf16* base = qkv + (size_t)w * 64 * (3 * HDIM) + hb * 64;
    for (int ch = tid; ch < 512; ch += 128) {
        int r = ch >> 3, c = (ch & 7) * 8;
        const bf16* rp = base + (size_t)r * (3 * HDIM);
        CP_ASYNC16(sptr(&qs[r][c]), rp + c);
        CP_ASYNC16(sptr(&ks[r][c]), rp + HDIM + c);
        CP_ASYNC16(sptr(&vs[r][c]), rp + 2 * HDIM + c);
    }
    asm volatile("cp.async.commit_group;\n" ::: "memory");
    asm volatile("cp.async.wait_group 0;\n" ::: "memory");
    __syncthreads();

    int co = hh * 32;

    float sacc[2][8][4];
#pragma unroll
    for (int mi = 0; mi < 2; mi++)
#pragma unroll
        for (int ni = 0; ni < 8; ni++)
#pragma unroll
            for (int r = 0; r < 4; r++) sacc[mi][ni][r] = 0.f;

#pragma unroll
    for (int kk = 0; kk < 2; kk++) {
        int k0 = co + kk * 16;
        unsigned af[2][4];
#pragma unroll
        for (int mi = 0; mi < 2; mi++) {
            unsigned addr = sptr(&qs[wr * 32 + mi * 16 + (lane & 15)][k0 + (lane >> 4) * 8]);
            asm volatile("ldmatrix.sync.aligned.m8n8.x4.shared.b16 {%0,%1,%2,%3},[%4];"
                : "=r"(af[mi][0]), "=r"(af[mi][1]), "=r"(af[mi][2]), "=r"(af[mi][3])
                : "r"(addr));
        }
        unsigned bf[8][2];
#pragma unroll
        for (int ni = 0; ni < 8; ni++) {
            unsigned addr = sptr(&ks[ni * 8 + (lane & 7)][k0 + ((lane >> 3) & 1) * 8]);
            asm volatile("ldmatrix.sync.aligned.m8n8.x2.shared.b16 {%0,%1},[%2];"
                : "=r"(bf[ni][0]), "=r"(bf[ni][1]) : "r"(addr));
        }
#pragma unroll
        for (int mi = 0; mi < 2; mi++)
#pragma unroll
            for (int ni = 0; ni < 8; ni++)
                asm volatile("mma.sync.aligned.m16n8k16.row.col.f32.bf16.bf16.f32 "
                    "{%0,%1,%2,%3},{%4,%5,%6,%7},{%8,%9},{%0,%1,%2,%3};"
                    : "+f"(sacc[mi][ni][0]), "+f"(sacc[mi][ni][1]),
                      "+f"(sacc[mi][ni][2]), "+f"(sacc[mi][ni][3])
                    : "r"(af[mi][0]), "r"(af[mi][1]), "r"(af[mi][2]), "r"(af[mi][3]),
                      "r"(bf[ni][0]), "r"(bf[ni][1]));
    }

    const float scale = 0.17677669529663687f;
    int lq  = lane >> 2;
    int lc2 = (lane & 3) * 2;
#pragma unroll
    for (int mi = 0; mi < 2; mi++) {
#pragma unroll
        for (int hf = 0; hf < 2; hf++) {
            int l = wr * 32 + mi * 16 + hf * 8 + lq;
            int il = l >> 3, jl = l & 7;
            int rgl = rg[l];
            float mx = -1e30f;
#pragma unroll
            for (int ni = 0; ni < 8; ni++) {
#pragma unroll
                for (int j = 0; j < 2; j++) {
                    int m = ni * 8 + lc2 + j;
                    int im = m >> 3, jm = m & 7;
                    float v = sacc[mi][ni][hf * 2 + j] * scale
                            + tbl[hh][(il - im + 7) * 15 + (jl - jm + 7)];
                    if (rg[m] != rgl) v = -1e30f;
                    sacc[mi][ni][hf * 2 + j] = v;
                    mx = fmaxf(mx, v);
                }
            }
            mx = fmaxf(mx, __shfl_xor_sync(0xffffffffu, mx, 1));
            mx = fmaxf(mx, __shfl_xor_sync(0xffffffffu, mx, 2));
            float sum = 0.f;
#pragma unroll
            for (int ni = 0; ni < 8; ni++) {
#pragma unroll
                for (int j = 0; j < 2; j++) {
                    float e = __expf(sacc[mi][ni][hf * 2 + j] - mx);
                    sacc[mi][ni][hf * 2 + j] = e;
                    sum += e;
                }
            }
            sum += __shfl_xor_sync(0xffffffffu, sum, 1);
            sum += __shfl_xor_sync(0xffffffffu, sum, 2);
            float inv = 1.f / sum;
#pragma unroll
            for (int ni = 0; ni < 8; ni++) {
                sacc[mi][ni][hf * 2 + 0] *= inv;
                sacc[mi][ni][hf * 2 + 1] *= inv;
            }
        }
    }

    unsigned pfr[2][4][4];
#pragma unroll
    for (int mi = 0; mi < 2; mi++)
#pragma unroll
        for (int q = 0; q < 4; q++) {
            pfr[mi][q][0] = packbf(sacc[mi][2 * q][0],     sacc[mi][2 * q][1]);
            pfr[mi][q][1] = packbf(sacc[mi][2 * q][2],     sacc[mi][2 * q][3]);
            pfr[mi][q][2] = packbf(sacc[mi][2 * q + 1][0], sacc[mi][2 * q + 1][1]);
            pfr[mi][q][3] = packbf(sacc[mi][2 * q + 1][2], sacc[mi][2 * q + 1][3]);
        }

    float oacc[2][4][4];
#pragma unroll
    for (int mi = 0; mi < 2; mi++)
#pragma unroll
        for (int nj = 0; nj < 4; nj++)
#pragma unroll
            for (int r = 0; r < 4; r++) oacc[mi][nj][r] = 0.f;

#pragma unroll
    for (int q = 0; q < 4; q++) {
        unsigned bv[4][2];
#pragma unroll
        for (int nj = 0; nj < 4; nj++) {
            unsigned addr = sptr(&vs[q * 16 + (lane & 15)][co + nj * 8]);
            asm volatile("ldmatrix.sync.aligned.m8n8.x2.trans.shared.b16 {%0,%1},[%2];"
                : "=r"(bv[nj][0]), "=r"(bv[nj][1]) : "r"(addr));
        }
#pragma unroll
        for (int mi = 0; mi < 2; mi++)
#pragma unroll
            for (int nj = 0; nj < 4; nj++)
                asm volatile("mma.sync.aligned.m16n8k16.row.col.f32.bf16.bf16.f32 "
                    "{%0,%1,%2,%3},{%4,%5,%6,%7},{%8,%9},{%0,%1,%2,%3};"
                    : "+f"(oacc[mi][nj][0]), "+f"(oacc[mi][nj][1]),
                      "+f"(oacc[mi][nj][2]), "+f"(oacc[mi][nj][3])
                    : "r"(pfr[mi][q][0]), "r"(pfr[mi][q][1]), "r"(pfr[mi][q][2]), "r"(pfr[mi][q][3]),
                      "r"(bv[nj][0]), "r"(bv[nj][1]));
    }

    int hgl = hb * 2 + hh;
#pragma unroll
    for (int mi = 0; mi < 2; mi++)
#pragma unroll
        for (int hf = 0; hf < 2; hf++) {
            int l = wr * 32 + mi * 16 + hf * 8 + lq;
            uint8_t* op = out + (size_t)(w * 64 + l) * HDIM + hgl * 32 + lc2;
#pragma unroll
            for (int nj = 0; nj < 4; nj++)
                *(unsigned short*)(op + nj * 8) =
                    pack8(oacc[mi][nj][hf * 2 + 0], oacc[mi][nj][hf * 2 + 1]);
        }
}

// ---------------- launch -----------------------------------------------------
extern "C" void kernel_launch(void* const* d_in, const int* in_sizes, int n_in,
                              void* d_out, int out_size)
{
    (void)in_sizes; (void)n_in; (void)out_size;
    const float* x     = (const float*)d_in[0];
    const float* n1w   = (const float*)d_in[1];
    const float* n1b   = (const float*)d_in[2];
    const float* qkvw  = (const float*)d_in[3];
    const float* qkvb  = (const float*)d_in[4];
    const float* projw = (const float*)d_in[5];
    const float* projb = (const float*)d_in[6];
    const float* relt  = (const float*)d_in[7];
    const float* g1    = (const float*)d_in[8];
    const float* n2w   = (const float*)d_in[9];
    const float* n2b   = (const float*)d_in[10];
    const float* fc1w  = (const float*)d_in[11];
    const float* fc1b  = (const float*)d_in[12];
    const float* fc2w  = (const float*)d_in[13];
    const float* fc2b  = (const float*)d_in[14];
    const float* g2    = (const float*)d_in[15];
    float* out = (float*)d_out;

    float *p_win, *p_o1;
    bf16 *p_qkvb;
    uint8_t *p_xn8, *p_att8, *p_h8, *p_wq8, *p_wp8, *p_w18, *p_w28;
    cudaGetSymbolAddress((void**)&p_win,  g_win);
    cudaGetSymbolAddress((void**)&p_o1,   g_o1);
    cudaGetSymbolAddress((void**)&p_xn8,  g_xn8);
    cudaGetSymbolAddress((void**)&p_qkvb, g_qkvb);
    cudaGetSymbolAddress((void**)&p_att8, g_att8);
    cudaGetSymbolAddress((void**)&p_h8,   g_h8);
    cudaGetSymbolAddress((void**)&p_wq8,  g_wq8);
    cudaGetSymbolAddress((void**)&p_wp8,  g_wp8);
    cudaGetSymbolAddress((void**)&p_w18,  g_w18);
    cudaGetSymbolAddress((void**)&p_w28,  g_w28);

    cudaFuncSetAttribute(qgemm_kernel<0, bf16>,
        cudaFuncAttributeMaxDynamicSharedMemorySize, QSMEM);
    cudaFuncSetAttribute(qgemm_kernel<1, uint8_t>,
        cudaFuncAttributeMaxDynamicSharedMemorySize, QSMEM);
    cudaFuncSetAttribute(qgemm_kernel<2, float>,
        cudaFuncAttributeMaxDynamicSharedMemorySize, QSMEM);

    dim3 tp(32, 8);
    // weight transpose + fp8 quantize (scaled x32)
    wtrans_kernel<<<dim3(HDIM / 32, 3 * HDIM / 32), tp>>>(qkvw, p_wq8, HDIM, 3 * HDIM);
    wtrans_kernel<<<dim3(HDIM / 32, HDIM / 32), tp>>>(projw, p_wp8, HDIM, HDIM);
    wtrans_kernel<<<dim3(HDIM / 32, 4 * HDIM / 32), tp>>>(fc1w, p_w18, HDIM, 4 * HDIM);
    wtrans_kernel<<<dim3(4 * HDIM / 32, HDIM / 32), tp>>>(fc2w, p_w28, 4 * HDIM, HDIM);

    partition_kernel<<<dim3(NTOK / 32, HDIM / 32), tp>>>(x, p_win);
    ln_kernel<<<NTOK / 8, 256>>>(p_win, p_xn8, n1w, n1b);
    qgemm_kernel<0, bf16><<<dim3(3 * HDIM / QBN, NTOK / QBM), 256, QSMEM>>>(
        p_xn8, p_wq8, qkvb, p_qkvb, NTOK, 3 * HDIM, HDIM, nullptr, nullptr);
    attn_mma_kernel<<<dim3(NW, 8), 128>>>(p_qkvb, relt, p_att8);
    qgemm_kernel<2, float><<<dim3(HDIM / QBN, NTOK / QBM), 256, QSMEM>>>(
        p_att8, p_wp8, projb, p_o1, NTOK, HDIM, HDIM, p_win, g1);
    ln_kernel<<<NTOK / 8, 256>>>(p_o1, p_xn8, n2w, n2b);
    qgemm_kernel<1, uint8_t><<<dim3(4 * HDIM / QBN, NTOK / QBM), 256, QSMEM>>>(
        p_xn8, p_w18, fc1b, p_h8, NTOK, 4 * HDIM, HDIM, nullptr, nullptr);
    qgemm_kernel<2, float><<<dim3(HDIM / QBN, NTOK / QBM), 256, QSMEM>>>(
        p_h8, p_w28, fc2b, p_win, NTOK, HDIM, 4 * HDIM, p_o1, g2);
    reverse_kernel<<<dim3(NTOK / 32, HDIM / 32), tp>>>(p_win, out);
}